// round 17
// baseline (speedup 1.0000x reference)
#include <cuda_runtime.h>
#include <cstdint>

// Output: [B=64, SRC_XLEN=16000, D=128] fp32.
// Rows r with (r % 4000) < 1000 get x[b, r % 4000, :]; all other rows zero.
//
// R14 (fire-and-forget zero stores, best: 84.48us) + R6's fill amortization:
//  - Zero path: 2560 CTAs. Each fills a 30 KiB SMEM zero buffer ONCE, then
//    issues FIVE contiguous cp.async.bulk stores (150 KiB contiguous zeros)
//    and exits WITHOUT waiting. Safety: the staging buffer only ever holds
//    zeros (it is the kernel's only SMEM writer), so a late TMA read of
//    reallocated SMEM still reads zeros; stores drain by kernel end.
//    SMEM STS fill traffic: 384 MiB -> 77 MiB.
//  - Copy path: 8000 CTAs. Each thread: 1 LDG.128 of x, 4 STG.128 to the
//    four segment destinations (x read exactly once from DRAM).

static constexpr int B = 64;
static constexpr int SRC_XLEN = 16000;
static constexpr int L = 1000;
static constexpr int SEG_STRIDE = 4000;
static constexpr int D4 = 32;                   // float4 per row
static constexpr int ROW_BYTES = 512;

static constexpr int CHUNK_ROWS = 60;
static constexpr int CHUNK_BYTES = CHUNK_ROWS * ROW_BYTES;    // 30720
static constexpr int STORES_PER_CTA = 5;                      // 300 rows covered
static constexpr int CTAS_PER_REGION = 3000 / (CHUNK_ROWS * STORES_PER_CTA); // 10
static constexpr int N_ZERO_BLOCKS = B * 4 * CTAS_PER_REGION; // 2560
static constexpr int N_COPY_BLOCKS = (B * L * D4) / 256;      // 8000
static constexpr int N_BLOCKS = N_ZERO_BLOCKS + N_COPY_BLOCKS; // 10560
// 10560 = 320 * 33; per group of 33: lanes 0..24 copy, lanes 25..32 zero.

static constexpr int F4_PER_SEG = SEG_STRIDE * D4;            // 128000

__global__ __launch_bounds__(256) void seg_zero_pad_kernel(
    const float4* __restrict__ x,   // [64, 1000, 32] float4
    float4* __restrict__ out        // [64, 16000, 32] float4
) {
    __shared__ __align__(128) float4 zbuf[CHUNK_BYTES / 16];   // 30 KiB of zeros

    const int bid = blockIdx.x;
    const int t = threadIdx.x;
    const int grp = bid / 33;
    const int lane = bid % 33;

    if (lane >= 25) {
        // ---- zero block: fill once, FIVE contiguous fire-and-forget bulk stores ----
        const int zid = grp * 8 + (lane - 25);            // 0 .. 2559
        const int region = zid / CTAS_PER_REGION;         // 0 .. 255
        const int j = zid - region * CTAS_PER_REGION;     // 0 .. 9
        const int batch = region >> 2;
        const int seg = region & 3;

        const size_t dst_base = (size_t)batch * SRC_XLEN * ROW_BYTES
                              + (size_t)(seg * SEG_STRIDE + L) * ROW_BYTES
                              + (size_t)j * (STORES_PER_CTA * CHUNK_BYTES);

        const float4 z = make_float4(0.f, 0.f, 0.f, 0.f);
        #pragma unroll
        for (int i = t; i < CHUNK_BYTES / 16; i += 256) zbuf[i] = z;
        __syncthreads();

        if (t == 0) {
            unsigned saddr;
            asm("{ .reg .u64 tmp; cvta.to.shared.u64 tmp, %1; cvt.u32.u64 %0, tmp; }"
                : "=r"(saddr) : "l"(zbuf));
            asm volatile("fence.proxy.async.shared::cta;" ::: "memory");
            #pragma unroll
            for (int s = 0; s < STORES_PER_CTA; s++) {
                unsigned long long gptr = (unsigned long long)
                    __cvta_generic_to_global((char*)out + dst_base
                                             + (size_t)s * CHUNK_BYTES);
                asm volatile(
                    "cp.async.bulk.global.shared::cta.bulk_group [%0], [%1], %2;"
                    :: "l"(gptr), "r"(saddr), "r"((unsigned)CHUNK_BYTES) : "memory");
            }
            asm volatile("cp.async.bulk.commit_group;" ::: "memory");
            // NO wait: CTA exits immediately; stores drain in the background.
        }
    } else {
        // ---- copy block: load x once, store to 4 segments ----
        const int cid = grp * 25 + lane;                  // 0 .. 7999
        const int gtid = cid * 256 + t;                   // 0 .. 2,047,999
        const int d4 = gtid & 31;
        const int rowflat = gtid >> 5;                    // batch * L + r
        const int batch = rowflat / L;
        const int r = rowflat - batch * L;

        const float4 v = __ldg(&x[gtid]);
        float4* dst = out + ((size_t)batch * SRC_XLEN + r) * D4 + d4;
        #pragma unroll
        for (int s = 0; s < 4; s++) {
            dst[(size_t)s * F4_PER_SEG] = v;
        }
    }
}

extern "C" void kernel_launch(void* const* d_in, const int* in_sizes, int n_in,
                              void* d_out, int out_size) {
    const float4* x = (const float4*)d_in[0];
    float4* out = (float4*)d_out;
    seg_zero_pad_kernel<<<N_BLOCKS, 256>>>(x, out);
}